// round 1
// baseline (speedup 1.0000x reference)
#include <cuda_runtime.h>
#include <math_constants.h>

#define NROWS 16384
#define D 256
#define KCB 8192
#define NSPLIT 4
#define CODES_PER_SPLIT (KCB / NSPLIT)
#define TM 128
#define TN 128
#define KC 16
#define NPART (NROWS / 8)

__device__ float g_codenorm[KCB];
__device__ float g_minval[NSPLIT][NROWS];
__device__ int   g_minidx[NSPLIT][NROWS];
__device__ float g_losspart[NPART];

// K0: ||e||^2 per codebook row. One warp per row.
__global__ void codenorm_kernel(const float* __restrict__ cb) {
    int warp = threadIdx.x >> 5;
    int lane = threadIdx.x & 31;
    int row  = blockIdx.x * 8 + warp;
    const float4* c4 = (const float4*)(cb + (size_t)row * D);
    float s = 0.f;
#pragma unroll
    for (int l = 0; l < 2; l++) {
        float4 v = c4[lane + 32 * l];
        s += v.x * v.x + v.y * v.y + v.z * v.z + v.w * v.w;
    }
#pragma unroll
    for (int o = 16; o > 0; o >>= 1) s += __shfl_down_sync(0xffffffffu, s, o);
    if (lane == 0) g_codenorm[row] = s;
}

// K1: fused GEMM (z @ cb^T) + running argmin over a code split.
// grid = (NSPLIT, NROWS/TM), block = 256 (16x16 threads, 8x8 micro-tile).
__global__ void __launch_bounds__(256, 2) dist_argmin_kernel(
    const float* __restrict__ z, const float* __restrict__ cb) {
    __shared__ float As[KC][TM];
    __shared__ float Bs[KC][TN];
    __shared__ float sMinV[TM][16];
    __shared__ int   sMinI[TM][16];

    const int tid = threadIdx.x;
    const int tx = tid & 15;
    const int ty = tid >> 4;
    const int rowBase   = blockIdx.y * TM;
    const int codeBase0 = blockIdx.x * CODES_PER_SPLIT;

    float minv[8];
    int   mini[8];
#pragma unroll
    for (int i = 0; i < 8; i++) { minv[i] = CUDART_INF_F; mini[i] = 0; }

    for (int ct = 0; ct < CODES_PER_SPLIT; ct += TN) {
        const int codeBase = codeBase0 + ct;
        float acc[8][8];
#pragma unroll
        for (int i = 0; i < 8; i++)
#pragma unroll
            for (int j = 0; j < 8; j++) acc[i][j] = 0.f;

        for (int k0 = 0; k0 < D; k0 += KC) {
            __syncthreads();
#pragma unroll
            for (int l = 0; l < 2; l++) {
                int id = l * 256 + tid;          // 0..511
                int r  = id >> 2;
                int k4 = (id & 3) << 2;
                float4 va = *(const float4*)(z  + (size_t)(rowBase  + r) * D + k0 + k4);
                As[k4 + 0][r] = va.x; As[k4 + 1][r] = va.y;
                As[k4 + 2][r] = va.z; As[k4 + 3][r] = va.w;
                float4 vb = *(const float4*)(cb + (size_t)(codeBase + r) * D + k0 + k4);
                Bs[k4 + 0][r] = vb.x; Bs[k4 + 1][r] = vb.y;
                Bs[k4 + 2][r] = vb.z; Bs[k4 + 3][r] = vb.w;
            }
            __syncthreads();
#pragma unroll
            for (int k = 0; k < KC; k++) {
                float4 a0 = *(const float4*)&As[k][ty * 8];
                float4 a1 = *(const float4*)&As[k][ty * 8 + 4];
                float4 b0 = *(const float4*)&Bs[k][tx * 8];
                float4 b1 = *(const float4*)&Bs[k][tx * 8 + 4];
                float a[8] = {a0.x, a0.y, a0.z, a0.w, a1.x, a1.y, a1.z, a1.w};
                float b[8] = {b0.x, b0.y, b0.z, b0.w, b1.x, b1.y, b1.z, b1.w};
#pragma unroll
                for (int i = 0; i < 8; i++)
#pragma unroll
                    for (int j = 0; j < 8; j++)
                        acc[i][j] = fmaf(a[i], b[j], acc[i][j]);
            }
        }
        // epilogue: dist = ||e||^2 - 2*dot, running argmin (strict <, idx ascending)
#pragma unroll
        for (int j = 0; j < 8; j++) {
            int   cidx = codeBase + tx * 8 + j;
            float cn   = __ldg(&g_codenorm[cidx]);
#pragma unroll
            for (int i = 0; i < 8; i++) {
                float d = fmaf(-2.f, acc[i][j], cn);
                if (d < minv[i]) { minv[i] = d; mini[i] = cidx; }
            }
        }
    }

    __syncthreads();
#pragma unroll
    for (int i = 0; i < 8; i++) {
        sMinV[ty * 8 + i][tx] = minv[i];
        sMinI[ty * 8 + i][tx] = mini[i];
    }
    __syncthreads();
    if (tid < TM) {
        float bv = sMinV[tid][0];
        int   bi = sMinI[tid][0];
#pragma unroll
        for (int t = 1; t < 16; t++) {
            float v  = sMinV[tid][t];
            int   ii = sMinI[tid][t];
            if (v < bv || (v == bv && ii < bi)) { bv = v; bi = ii; }
        }
        g_minval[blockIdx.x][rowBase + tid] = bv;
        g_minidx[blockIdx.x][rowBase + tid] = bi;
    }
}

// K2: reduce splits -> idx; write z_e copy + gathered z_q; per-block loss partials.
// One warp per row, 8 rows per block.
__global__ void gather_kernel(const float* __restrict__ z,
                              const float* __restrict__ cb,
                              float* __restrict__ out) {
    const int lane = threadIdx.x & 31;
    const int warp = threadIdx.x >> 5;
    const int row  = blockIdx.x * 8 + warp;
    __shared__ float wsum[8];

    int bi = 0;
    if (lane == 0) {
        float bv = g_minval[0][row]; bi = g_minidx[0][row];
#pragma unroll
        for (int s = 1; s < NSPLIT; s++) {
            float v  = g_minval[s][row];
            int   ii = g_minidx[s][row];
            if (v < bv || (v == bv && ii < bi)) { bv = v; bi = ii; }
        }
    }
    bi = __shfl_sync(0xffffffffu, bi, 0);

    const float4* z4 = (const float4*)(z  + (size_t)row * D);
    const float4* c4 = (const float4*)(cb + (size_t)bi  * D);
    float* out_ze = out + (size_t)row * D;
    float* out_zq = out + (size_t)NROWS * D + 1 + (size_t)row * D; // +1: after loss slot -> unaligned, scalar stores
    float s = 0.f;
#pragma unroll
    for (int l = 0; l < 2; l++) {
        int f = lane + 32 * l;
        float4 ze = z4[f];
        float4 zq = c4[f];
        *(float4*)(out_ze + f * 4) = ze;
        out_zq[f * 4 + 0] = zq.x; out_zq[f * 4 + 1] = zq.y;
        out_zq[f * 4 + 2] = zq.z; out_zq[f * 4 + 3] = zq.w;
        float dx = zq.x - ze.x, dy = zq.y - ze.y, dz = zq.z - ze.z, dw = zq.w - ze.w;
        s += dx * dx + dy * dy + dz * dz + dw * dw;
    }
#pragma unroll
    for (int o = 16; o > 0; o >>= 1) s += __shfl_down_sync(0xffffffffu, s, o);
    if (lane == 0) wsum[warp] = s;
    __syncthreads();
    if (threadIdx.x == 0) {
        float t = 0.f;
#pragma unroll
        for (int w = 0; w < 8; w++) t += wsum[w];
        g_losspart[blockIdx.x] = t;
    }
}

// K3: deterministic final loss reduction. loss = 2 * mean((z_q - z_e)^2)
__global__ void loss_kernel(float* __restrict__ out) {
    __shared__ float s[256];
    float t = 0.f;
    for (int i = threadIdx.x; i < NPART; i += 256) t += g_losspart[i];
    s[threadIdx.x] = t;
    __syncthreads();
    for (int o = 128; o > 0; o >>= 1) {
        if (threadIdx.x < o) s[threadIdx.x] += s[threadIdx.x + o];
        __syncthreads();
    }
    if (threadIdx.x == 0)
        out[(size_t)NROWS * D] = 2.f * s[0] / (float)((size_t)NROWS * D);
}

extern "C" void kernel_launch(void* const* d_in, const int* in_sizes, int n_in,
                              void* d_out, int out_size) {
    const float* z  = (const float*)d_in[0];
    const float* cb = (const float*)d_in[1];
    float* out = (float*)d_out;

    codenorm_kernel<<<KCB / 8, 256>>>(cb);
    dist_argmin_kernel<<<dim3(NSPLIT, NROWS / TM), 256>>>(z, cb);
    gather_kernel<<<NROWS / 8, 256>>>(z, cb, out);
    loss_kernel<<<1, 256>>>(out);
}

// round 3
// speedup vs baseline: 3.2963x; 3.2963x over previous
#include <cuda_runtime.h>
#include <cuda_bf16.h>
#include <math_constants.h>
#include <cstdint>

#define NROWS 16384
#define DIM   256
#define KCB   8192
#define MT    64                 /* rows per CTA          */
#define MTILES (NROWS / MT)      /* 256 CTAs              */
#define NTILES (KCB / 128)       /* 64 code tiles         */
#define NPART (NROWS / 8)

/* GEMM smem layout (dynamic) */
#define SA_OFF  0                /* 8 chunks x 8KB  = 65536 (A hi 0-3 | lo 4-7) */
#define SB_OFF  65536            /* 2 x 16KB B double buffer                    */
#define SCN_OFF 98304            /* 2 x 512B codenorm tiles                     */
#define GEMM_SMEM 99328

/* ------------- device globals (no allocs allowed) ------------- */
__device__ unsigned char g_zt[MTILES * 65536];          /* 16MB pre-swizzled A  */
__device__ unsigned char g_cbt[NTILES * 8 * 16384];     /*  8MB pre-swizzled B  */
__device__ float g_codenorm[KCB];
__device__ int   g_i1[NROWS];
__device__ int   g_i2[NROWS];
__device__ float g_losspart[NPART];

/* ------------- helpers ------------- */
__device__ __forceinline__ unsigned smem_u32(const void* p) {
    unsigned a;
    asm("{ .reg .u64 t; cvta.to.shared.u64 t, %1; cvt.u32.u64 %0, t; }" : "=r"(a) : "l"(p));
    return a;
}
__device__ __forceinline__ void cp_async16(unsigned dst, const void* src) {
    asm volatile("cp.async.cg.shared.global [%0], [%1], 16;" :: "r"(dst), "l"(src) : "memory");
}
__device__ __forceinline__ void ldsm_x4(unsigned* r, unsigned addr) {
    asm volatile("ldmatrix.sync.aligned.m8n8.x4.shared.b16 {%0,%1,%2,%3}, [%4];"
                 : "=r"(r[0]), "=r"(r[1]), "=r"(r[2]), "=r"(r[3]) : "r"(addr));
}
__device__ __forceinline__ void ldsm_x4_t(unsigned* r, unsigned addr) {
    asm volatile("ldmatrix.sync.aligned.m8n8.x4.trans.shared.b16 {%0,%1,%2,%3}, [%4];"
                 : "=r"(r[0]), "=r"(r[1]), "=r"(r[2]), "=r"(r[3]) : "r"(addr));
}
__device__ __forceinline__ void mma16816(float (&c)[4], const unsigned* a, unsigned b0, unsigned b1) {
    asm volatile("mma.sync.aligned.m16n8k16.row.col.f32.bf16.bf16.f32 "
                 "{%0,%1,%2,%3}, {%4,%5,%6,%7}, {%8,%9}, {%0,%1,%2,%3};"
                 : "+f"(c[0]), "+f"(c[1]), "+f"(c[2]), "+f"(c[3])
                 : "r"(a[0]), "r"(a[1]), "r"(a[2]), "r"(a[3]), "r"(b0), "r"(b1));
}
__device__ __forceinline__ void split2(float x, unsigned short& h, unsigned short& l) {
    __nv_bfloat16 bh = __float2bfloat16_rn(x);
    __nv_bfloat16 bl = __float2bfloat16_rn(x - __bfloat162float(bh));
    h = __bfloat16_as_ushort(bh);
    l = __bfloat16_as_ushort(bl);
}
__device__ __forceinline__ void top2_update(float& v1, int& i1, float& v2, int& i2, float d, int c) {
    if (d < v2) {
        if (d < v1) { v2 = v1; i2 = i1; v1 = d; i1 = c; }
        else        { v2 = d;  i2 = c; }
    }
}
__device__ __forceinline__ void top2_merge(float& v1, int& i1, float& v2, int& i2,
                                           float u1, int j1, float u2, int j2) {
    bool ult = (u1 < v1) || (u1 == v1 && j1 < i1);
    float w1 = ult ? u1 : v1; int k1 = ult ? j1 : i1;
    float lv = ult ? v1 : u1; int li = ult ? i1 : j1;  /* loser of firsts   */
    float ov = ult ? u2 : v2; int oi = ult ? j2 : i2;  /* winner's second   */
    bool s2 = (lv < ov) || (lv == ov && li < oi);
    v1 = w1; i1 = k1;
    v2 = s2 ? lv : ov; i2 = s2 ? li : oi;
}

/* ---------- preprocess: z -> swizzled bf16 hi/lo tiles ---------- */
__global__ void split_z_kernel(const float* __restrict__ z) {
    const int id = blockIdx.x * 256 + threadIdx.x;   /* 0..524287 */
    const int row = id >> 5;
    const int j = id & 31;                            /* 8-float group */
    const float* src = z + (size_t)row * DIM + j * 8;
    float4 f0 = __ldg((const float4*)src);
    float4 f1 = __ldg((const float4*)(src + 4));
    float v[8] = {f0.x, f0.y, f0.z, f0.w, f1.x, f1.y, f1.z, f1.w};
    unsigned short hv[8], lv[8];
#pragma unroll
    for (int e = 0; e < 8; e++) split2(v[e], hv[e], lv[e]);
    const int m = row & 63;
    const int kc = j >> 3, c = j & 7;
    size_t base = (size_t)(row >> 6) * 65536 + (size_t)kc * 8192 + m * 128 + ((c ^ (m & 7)) << 4);
    *(uint4*)(g_zt + base)            = *(uint4*)hv;
    *(uint4*)(g_zt + base + 4 * 8192) = *(uint4*)lv;
}

/* ---------- preprocess: codebook -> k-major swizzled bf16 hi/lo chunks ---------- */
__global__ void split_cb_kernel(const float* __restrict__ cb) {
    __shared__ __nv_bfloat16 sh[64][136];
    __shared__ __nv_bfloat16 sl[64][136];
    const int nt = blockIdx.x >> 2;
    const int kc = blockIdx.x & 3;
    const int tid = threadIdx.x;
    const int n = tid >> 1, half = tid & 1;
    const float* src = cb + (size_t)(nt * 128 + n) * DIM + kc * 64 + half * 32;
#pragma unroll
    for (int j = 0; j < 8; j++) {
        float4 f = __ldg((const float4*)(src + j * 4));
        float vv[4] = {f.x, f.y, f.z, f.w};
#pragma unroll
        for (int e = 0; e < 4; e++) {
            int k = half * 32 + j * 4 + e;
            unsigned short h, l;
            split2(vv[e], h, l);
            sh[k][n] = __ushort_as_bfloat16(h);
            sl[k][n] = __ushort_as_bfloat16(l);
        }
    }
    __syncthreads();
    unsigned char* dhi = g_cbt + ((size_t)nt * 8 + kc) * 16384;
    unsigned char* dlo = dhi + 4 * 16384;
#pragma unroll
    for (int i = 0; i < 4; i++) {
        int u = tid + i * 256;
        int k = u >> 4, c = u & 15;
        unsigned short hv[8], lv[8];
#pragma unroll
        for (int e = 0; e < 8; e++) {
            hv[e] = __bfloat16_as_ushort(sh[k][c * 8 + e]);
            lv[e] = __bfloat16_as_ushort(sl[k][c * 8 + e]);
        }
        size_t off = (size_t)k * 256 + ((c ^ (k & 7)) * 16);
        *(uint4*)(dhi + off) = *(uint4*)hv;
        *(uint4*)(dlo + off) = *(uint4*)lv;
    }
}

/* ---------- exact fp32 codebook norms ---------- */
__global__ void codenorm_kernel(const float* __restrict__ cb) {
    int warp = threadIdx.x >> 5, lane = threadIdx.x & 31;
    int row = blockIdx.x * 8 + warp;
    const float4* c4 = (const float4*)(cb + (size_t)row * DIM);
    float s = 0.f;
#pragma unroll
    for (int l = 0; l < 2; l++) {
        float4 v = c4[lane + 32 * l];
        s += v.x * v.x + v.y * v.y + v.z * v.z + v.w * v.w;
    }
#pragma unroll
    for (int o = 16; o > 0; o >>= 1) s += __shfl_down_sync(0xffffffffu, s, o);
    if (lane == 0) g_codenorm[row] = s;
}

/* ---------- B-chunk producer ---------- */
__device__ __forceinline__ void issue_chunk(unsigned smb, int s, int tid) {
    const int nt = s >> 3, p = s & 7;
    const unsigned char* src = g_cbt + ((size_t)nt * 8 + p) * 16384 + tid * 16;
    unsigned dst = smb + SB_OFF + (s & 1) * 16384 + tid * 16;
#pragma unroll
    for (int i = 0; i < 4; i++) cp_async16(dst + i * 4096, src + (size_t)i * 4096);
    if (p == 0 && tid < 32)
        cp_async16(smb + SCN_OFF + (nt & 1) * 512 + tid * 16,
                   (const unsigned char*)g_codenorm + (size_t)nt * 512 + tid * 16);
    asm volatile("cp.async.commit_group;" ::: "memory");
}

/* ---------- one k64 x (64m x 128n) mma pass ---------- */
__device__ __forceinline__ void mma_pass(float (&acc)[2][4][4], unsigned smb,
                                         int achunk, int buf, int wm, int wn, int lane) {
    const unsigned abase = smb + SA_OFF + achunk * 8192;
    const unsigned bbase = smb + SB_OFF + buf * 16384;
    const int mlo = wm * 32 + (lane & 15);
    const int mhi = mlo + 16;
    const int klane = lane & 15;
    const int sel = lane >> 4;
#pragma unroll
    for (int ks = 0; ks < 4; ks++) {
        unsigned a0[4], a1[4], b0[4], b1[4];
        {
            int kc16 = ks * 2 + sel;
            ldsm_x4(a0, abase + mlo * 128 + ((kc16 ^ (mlo & 7)) << 4));
            ldsm_x4(a1, abase + mhi * 128 + ((kc16 ^ (mhi & 7)) << 4));
        }
        {
            int k = ks * 16 + klane;
            int cbase = wn * 4 + sel;
            ldsm_x4_t(b0, bbase + k * 256 + ((cbase ^ (k & 7)) << 4));
            ldsm_x4_t(b1, bbase + k * 256 + (((cbase + 2) ^ (k & 7)) << 4));
        }
        mma16816(acc[0][0], a0, b0[0], b0[1]);
        mma16816(acc[0][1], a0, b0[2], b0[3]);
        mma16816(acc[0][2], a0, b1[0], b1[1]);
        mma16816(acc[0][3], a0, b1[2], b1[3]);
        mma16816(acc[1][0], a1, b0[0], b0[1]);
        mma16816(acc[1][1], a1, b0[2], b0[3]);
        mma16816(acc[1][2], a1, b1[0], b1[1]);
        mma16816(acc[1][3], a1, b1[2], b1[3]);
    }
}

/* ---------- K1: bf16x3 tensor-core GEMM + fused top-2 argmin ---------- */
__global__ void __launch_bounds__(256, 2) vq_mma_kernel() {
    extern __shared__ __align__(128) unsigned char smem[];
    const unsigned smb = smem_u32(smem);
    const int tid = threadIdx.x;
    const int lane = tid & 31;
    const int w = tid >> 5;
    const int wm = w >> 2, wn = w & 3;
    const int mtile = blockIdx.x;

    { /* resident A (hi|lo, 64KB) */
        const unsigned char* src = g_zt + (size_t)mtile * 65536 + tid * 16;
        unsigned dst = smb + SA_OFF + tid * 16;
#pragma unroll
        for (int i = 0; i < 16; i++) cp_async16(dst + i * 4096, src + (size_t)i * 4096);
        asm volatile("cp.async.commit_group;" ::: "memory");
    }
    issue_chunk(smb, 0, tid);
    issue_chunk(smb, 1, tid);

    float acc[2][4][4];
#pragma unroll
    for (int i = 0; i < 2; i++)
#pragma unroll
        for (int j = 0; j < 4; j++)
#pragma unroll
            for (int r = 0; r < 4; r++) acc[i][j][r] = 0.f;
    float tv1[4], tv2[4];
    int ti1[4], ti2[4];
#pragma unroll
    for (int sl = 0; sl < 4; sl++) { tv1[sl] = CUDART_INF_F; tv2[sl] = CUDART_INF_F; ti1[sl] = 0; ti2[sl] = 0; }

    for (int s = 0; s < 8 * NTILES; s++) {
        if (s == 8 * NTILES - 1) asm volatile("cp.async.wait_group 0;" ::: "memory");
        else                     asm volatile("cp.async.wait_group 1;" ::: "memory");
        __syncthreads();
        const int p = s & 7, buf = s & 1;
        if (p < 4) {                             /* B hi chunk: A_hi then A_lo */
            mma_pass(acc, smb, p,     buf, wm, wn, lane);
            mma_pass(acc, smb, 4 + p, buf, wm, wn, lane);
        } else {                                 /* B lo chunk: A_hi */
            mma_pass(acc, smb, p - 4, buf, wm, wn, lane);
        }
        if (p == 7) {                            /* epilogue: dist + top-2 */
            const int nt = s >> 3;
            const float* cnp = (const float*)(smem + SCN_OFF + (nt & 1) * 512);
            const int colb = wn * 32 + 2 * (lane & 3);
#pragma unroll
            for (int ni = 0; ni < 4; ni++) {
                float cn0 = cnp[colb + ni * 8];
                float cn1 = cnp[colb + ni * 8 + 1];
                int c0 = nt * 128 + colb + ni * 8;
#pragma unroll
                for (int mi = 0; mi < 2; mi++) {
#pragma unroll
                    for (int h = 0; h < 2; h++) {
                        int sl = mi * 2 + h;
                        float d0 = fmaf(-2.f, acc[mi][ni][h * 2],     cn0);
                        float d1 = fmaf(-2.f, acc[mi][ni][h * 2 + 1], cn1);
                        top2_update(tv1[sl], ti1[sl], tv2[sl], ti2[sl], d0, c0);
                        top2_update(tv1[sl], ti1[sl], tv2[sl], ti2[sl], d1, c0 + 1);
                        acc[mi][ni][h * 2] = 0.f;
                        acc[mi][ni][h * 2 + 1] = 0.f;
                    }
                }
            }
        }
        __syncthreads();
        if (s + 2 < 8 * NTILES) issue_chunk(smb, s + 2, tid);
    }

    /* reduce over quad lanes (cols) */
#pragma unroll
    for (int off = 1; off <= 2; off <<= 1) {
#pragma unroll
        for (int sl = 0; sl < 4; sl++) {
            float u1 = __shfl_xor_sync(0xffffffffu, tv1[sl], off);
            int   j1 = __shfl_xor_sync(0xffffffffu, ti1[sl], off);
            float u2 = __shfl_xor_sync(0xffffffffu, tv2[sl], off);
            int   j2 = __shfl_xor_sync(0xffffffffu, ti2[sl], off);
            top2_merge(tv1[sl], ti1[sl], tv2[sl], ti2[sl], u1, j1, u2, j2);
        }
    }
    __syncthreads();
    float4* red = (float4*)(smem + SB_OFF);
    if ((lane & 3) == 0) {
#pragma unroll
        for (int sl = 0; sl < 4; sl++) {
            int row = wm * 32 + (sl >> 1) * 16 + (sl & 1) * 8 + (lane >> 2);
            red[row * 4 + wn] = make_float4(tv1[sl], __int_as_float(ti1[sl]),
                                            tv2[sl], __int_as_float(ti2[sl]));
        }
    }
    __syncthreads();
    if (tid < 64) {
        float4 e = red[tid * 4];
        float v1 = e.x, v2 = e.z;
        int i1 = __float_as_int(e.y), i2 = __float_as_int(e.w);
#pragma unroll
        for (int q = 1; q < 4; q++) {
            float4 f = red[tid * 4 + q];
            top2_merge(v1, i1, v2, i2, f.x, __float_as_int(f.y), f.z, __float_as_int(f.w));
        }
        g_i1[mtile * MT + tid] = i1;
        g_i2[mtile * MT + tid] = i2;
    }
}

/* ---------- K2: exact fp32 rescore of top-2 + gather + loss partials ---------- */
__global__ void rescore_gather_kernel(const float* __restrict__ z,
                                      const float* __restrict__ cb,
                                      float* __restrict__ out) {
    const int lane = threadIdx.x & 31, warp = threadIdx.x >> 5;
    const int row = blockIdx.x * 8 + warp;
    __shared__ float wsum[8];

    const int i1 = g_i1[row], i2 = g_i2[row];
    const float4* z4  = (const float4*)(z + (size_t)row * DIM);
    const float4* e14 = (const float4*)(cb + (size_t)i1 * DIM);
    const float4* e24 = (const float4*)(cb + (size_t)i2 * DIM);
    float4 a[2], b1[2], b2[2];
    float d1 = 0.f, d2 = 0.f;
#pragma unroll
    for (int l = 0; l < 2; l++) {
        int f = lane + 32 * l;
        a[l] = z4[f]; b1[l] = e14[f]; b2[l] = e24[f];
        d1 += a[l].x * b1[l].x + a[l].y * b1[l].y + a[l].z * b1[l].z + a[l].w * b1[l].w;
        d2 += a[l].x * b2[l].x + a[l].y * b2[l].y + a[l].z * b2[l].z + a[l].w * b2[l].w;
    }
#pragma unroll
    for (int o = 16; o > 0; o >>= 1) {
        d1 += __shfl_xor_sync(0xffffffffu, d1, o);
        d2 += __shfl_xor_sync(0xffffffffu, d2, o);
    }
    const float dist1 = fmaf(-2.f, d1, __ldg(&g_codenorm[i1]));
    const float dist2 = fmaf(-2.f, d2, __ldg(&g_codenorm[i2]));
    const bool take2 = (dist2 < dist1) || (dist2 == dist1 && i2 < i1);

    float* out_ze = out + (size_t)row * DIM;
    float* out_zq = out + (size_t)NROWS * DIM + 1 + (size_t)row * DIM;
    float s = 0.f;
#pragma unroll
    for (int l = 0; l < 2; l++) {
        int f = lane + 32 * l;
        float4 ze = a[l];
        float4 zq = take2 ? b2[l] : b1[l];
        *(float4*)(out_ze + f * 4) = ze;
        out_zq[f * 4 + 0] = zq.x; out_zq[f * 4 + 1] = zq.y;
        out_zq[f * 4 + 2] = zq.z; out_zq[f * 4 + 3] = zq.w;
        float dx = zq.x - ze.x, dy = zq.y - ze.y, dz = zq.z - ze.z, dw = zq.w - ze.w;
        s += dx * dx + dy * dy + dz * dz + dw * dw;
    }
#pragma unroll
    for (int o = 16; o > 0; o >>= 1) s += __shfl_down_sync(0xffffffffu, s, o);
    if (lane == 0) wsum[warp] = s;
    __syncthreads();
    if (threadIdx.x == 0) {
        float t = 0.f;
#pragma unroll
        for (int wv = 0; wv < 8; wv++) t += wsum[wv];
        g_losspart[blockIdx.x] = t;
    }
}

/* ---------- K3: deterministic final loss ---------- */
__global__ void loss_kernel(float* __restrict__ out) {
    __shared__ float s[256];
    float t = 0.f;
    for (int i = threadIdx.x; i < NPART; i += 256) t += g_losspart[i];
    s[threadIdx.x] = t;
    __syncthreads();
    for (int o = 128; o > 0; o >>= 1) {
        if (threadIdx.x < o) s[threadIdx.x] += s[threadIdx.x + o];
        __syncthreads();
    }
    if (threadIdx.x == 0)
        out[(size_t)NROWS * DIM] = 2.f * s[0] / (float)((size_t)NROWS * DIM);
}

extern "C" void kernel_launch(void* const* d_in, const int* in_sizes, int n_in,
                              void* d_out, int out_size) {
    const float* z  = (const float*)d_in[0];
    const float* cb = (const float*)d_in[1];
    float* out = (float*)d_out;

    cudaFuncSetAttribute(vq_mma_kernel, cudaFuncAttributeMaxDynamicSharedMemorySize, GEMM_SMEM);

    split_z_kernel<<<NROWS * 32 / 256, 256>>>(z);
    split_cb_kernel<<<NTILES * 4, 256>>>(cb);
    codenorm_kernel<<<KCB / 8, 256>>>(cb);
    vq_mma_kernel<<<MTILES, 256, GEMM_SMEM>>>();
    rescore_gather_kernel<<<NROWS / 8, 256>>>(z, cb, out);
    loss_kernel<<<1, 256>>>(out);
}

// round 4
// speedup vs baseline: 4.7601x; 1.4441x over previous
#include <cuda_runtime.h>
#include <cuda_bf16.h>
#include <math_constants.h>
#include <cstdint>

#define NROWS 16384
#define DIM   256
#define KCB   8192
#define MT    64                 /* rows per CTA          */
#define MTILES (NROWS / MT)      /* 256 CTAs              */
#define NTILES (KCB / 128)       /* 64 code tiles         */
#define NCHUNK (4 * NTILES)      /* 256 B hi chunks       */
#define NPART (NROWS / 8)

/* GEMM smem layout (dynamic) */
#define SA_OFF  0                /* 8 chunks x 8KB = 65536 (A hi 0-3 | lo 4-7) */
#define SB_OFF  65536            /* 2 x 16KB B double buffer / 16KB reduce     */
#define SCN_OFF 98304            /* 2 x 512B codenorm tiles                    */
#define GEMM_SMEM 99328

/* ------------- device globals (no allocs allowed) ------------- */
__device__ unsigned char g_zt[MTILES * 65536];          /* 16MB pre-swizzled A hi|lo */
__device__ unsigned char g_cbt[NTILES * 4 * 16384];     /*  4MB pre-swizzled B hi    */
__device__ float g_codenorm[KCB];
__device__ int   g_cand[NROWS * 4];
__device__ float g_losspart[NPART];

/* ------------- helpers ------------- */
__device__ __forceinline__ unsigned smem_u32(const void* p) {
    unsigned a;
    asm("{ .reg .u64 t; cvta.to.shared.u64 t, %1; cvt.u32.u64 %0, t; }" : "=r"(a) : "l"(p));
    return a;
}
__device__ __forceinline__ void cp_async16(unsigned dst, const void* src) {
    asm volatile("cp.async.cg.shared.global [%0], [%1], 16;" :: "r"(dst), "l"(src) : "memory");
}
__device__ __forceinline__ void ldsm_x4(unsigned* r, unsigned addr) {
    asm volatile("ldmatrix.sync.aligned.m8n8.x4.shared.b16 {%0,%1,%2,%3}, [%4];"
                 : "=r"(r[0]), "=r"(r[1]), "=r"(r[2]), "=r"(r[3]) : "r"(addr));
}
__device__ __forceinline__ void ldsm_x4_t(unsigned* r, unsigned addr) {
    asm volatile("ldmatrix.sync.aligned.m8n8.x4.trans.shared.b16 {%0,%1,%2,%3}, [%4];"
                 : "=r"(r[0]), "=r"(r[1]), "=r"(r[2]), "=r"(r[3]) : "r"(addr));
}
__device__ __forceinline__ void mma16816(float (&c)[4], const unsigned* a, unsigned b0, unsigned b1) {
    asm volatile("mma.sync.aligned.m16n8k16.row.col.f32.bf16.bf16.f32 "
                 "{%0,%1,%2,%3}, {%4,%5,%6,%7}, {%8,%9}, {%0,%1,%2,%3};"
                 : "+f"(c[0]), "+f"(c[1]), "+f"(c[2]), "+f"(c[3])
                 : "r"(a[0]), "r"(a[1]), "r"(a[2]), "r"(a[3]), "r"(b0), "r"(b1));
}
__device__ __forceinline__ void split2(float x, unsigned short& h, unsigned short& l) {
    __nv_bfloat16 bh = __float2bfloat16_rn(x);
    __nv_bfloat16 bl = __float2bfloat16_rn(x - __bfloat162float(bh));
    h = __bfloat16_as_ushort(bh);
    l = __bfloat16_as_ushort(bl);
}
__device__ __forceinline__ void top2_update(float& v1, int& i1, float& v2, int& i2, float d, int c) {
    if (d < v2) {
        if (d < v1) { v2 = v1; i2 = i1; v1 = d; i1 = c; }
        else        { v2 = d;  i2 = c; }
    }
}
__device__ __forceinline__ void ins4(float (&cv)[4], int (&ci)[4], float v, int i) {
#pragma unroll
    for (int j = 0; j < 4; j++) {
        bool lt = (v < cv[j]) || (v == cv[j] && i < ci[j]);
        float tv = lt ? cv[j] : v; int ti = lt ? ci[j] : i;
        if (lt) { cv[j] = v; ci[j] = i; }
        v = tv; i = ti;
    }
}

/* ---------- preprocess: z -> swizzled bf16 hi/lo tiles ---------- */
__global__ void split_z_kernel(const float* __restrict__ z) {
    const int id = blockIdx.x * 256 + threadIdx.x;
    const int row = id >> 5;
    const int j = id & 31;
    const float* src = z + (size_t)row * DIM + j * 8;
    float4 f0 = __ldg((const float4*)src);
    float4 f1 = __ldg((const float4*)(src + 4));
    float v[8] = {f0.x, f0.y, f0.z, f0.w, f1.x, f1.y, f1.z, f1.w};
    unsigned short hv[8], lv[8];
#pragma unroll
    for (int e = 0; e < 8; e++) split2(v[e], hv[e], lv[e]);
    const int m = row & 63;
    const int kc = j >> 3, c = j & 7;
    size_t base = (size_t)(row >> 6) * 65536 + (size_t)kc * 8192 + m * 128 + ((c ^ (m & 7)) << 4);
    *(uint4*)(g_zt + base)            = *(uint4*)hv;
    *(uint4*)(g_zt + base + 4 * 8192) = *(uint4*)lv;
}

/* ---------- preprocess: codebook -> k-major swizzled bf16 hi chunks ---------- */
__global__ void split_cb_kernel(const float* __restrict__ cb) {
    __shared__ __nv_bfloat16 sh[64][136];
    const int nt = blockIdx.x >> 2;
    const int kc = blockIdx.x & 3;
    const int tid = threadIdx.x;
    const int n = tid >> 1, half = tid & 1;
    const float* src = cb + (size_t)(nt * 128 + n) * DIM + kc * 64 + half * 32;
#pragma unroll
    for (int j = 0; j < 8; j++) {
        float4 f = __ldg((const float4*)(src + j * 4));
        float vv[4] = {f.x, f.y, f.z, f.w};
#pragma unroll
        for (int e = 0; e < 4; e++) {
            int k = half * 32 + j * 4 + e;
            sh[k][n] = __float2bfloat16_rn(vv[e]);
        }
    }
    __syncthreads();
    unsigned char* dhi = g_cbt + ((size_t)nt * 4 + kc) * 16384;
#pragma unroll
    for (int i = 0; i < 4; i++) {
        int u = tid + i * 256;
        int k = u >> 4, c = u & 15;
        unsigned short hv[8];
#pragma unroll
        for (int e = 0; e < 8; e++) hv[e] = __bfloat16_as_ushort(sh[k][c * 8 + e]);
        size_t off = (size_t)k * 256 + ((c ^ (k & 7)) * 16);
        *(uint4*)(dhi + off) = *(uint4*)hv;
    }
}

/* ---------- exact fp32 codebook norms ---------- */
__global__ void codenorm_kernel(const float* __restrict__ cb) {
    int warp = threadIdx.x >> 5, lane = threadIdx.x & 31;
    int row = blockIdx.x * 8 + warp;
    const float4* c4 = (const float4*)(cb + (size_t)row * DIM);
    float s = 0.f;
#pragma unroll
    for (int l = 0; l < 2; l++) {
        float4 v = c4[lane + 32 * l];
        s += v.x * v.x + v.y * v.y + v.z * v.z + v.w * v.w;
    }
#pragma unroll
    for (int o = 16; o > 0; o >>= 1) s += __shfl_down_sync(0xffffffffu, s, o);
    if (lane == 0) g_codenorm[row] = s;
}

/* ---------- B-chunk producer ---------- */
__device__ __forceinline__ void issue_chunk(unsigned smb, int s, int tid) {
    const int nt = s >> 2, p = s & 3;
    const unsigned char* src = g_cbt + ((size_t)nt * 4 + p) * 16384 + tid * 16;
    unsigned dst = smb + SB_OFF + (s & 1) * 16384 + tid * 16;
#pragma unroll
    for (int i = 0; i < 4; i++) cp_async16(dst + i * 4096, src + (size_t)i * 4096);
    if (p == 0 && tid < 32)
        cp_async16(smb + SCN_OFF + (nt & 1) * 512 + tid * 16,
                   (const unsigned char*)g_codenorm + (size_t)nt * 512 + tid * 16);
    asm volatile("cp.async.commit_group;" ::: "memory");
}

/* ---------- one k64 x (64m x 128n) mma pass ---------- */
__device__ __forceinline__ void mma_pass(float (&acc)[2][4][4], unsigned smb,
                                         int achunk, int buf, int wm, int wn, int lane) {
    const unsigned abase = smb + SA_OFF + achunk * 8192;
    const unsigned bbase = smb + SB_OFF + buf * 16384;
    const int mlo = wm * 32 + (lane & 15);
    const int mhi = mlo + 16;
    const int klane = lane & 15;
    const int sel = lane >> 4;
#pragma unroll
    for (int ks = 0; ks < 4; ks++) {
        unsigned a0[4], a1[4], b0[4], b1[4];
        {
            int kc16 = ks * 2 + sel;
            ldsm_x4(a0, abase + mlo * 128 + ((kc16 ^ (mlo & 7)) << 4));
            ldsm_x4(a1, abase + mhi * 128 + ((kc16 ^ (mhi & 7)) << 4));
        }
        {
            int k = ks * 16 + klane;
            int cbase = wn * 4 + sel;
            ldsm_x4_t(b0, bbase + k * 256 + ((cbase ^ (k & 7)) << 4));
            ldsm_x4_t(b1, bbase + k * 256 + (((cbase + 2) ^ (k & 7)) << 4));
        }
        mma16816(acc[0][0], a0, b0[0], b0[1]);
        mma16816(acc[0][1], a0, b0[2], b0[3]);
        mma16816(acc[0][2], a0, b1[0], b1[1]);
        mma16816(acc[0][3], a0, b1[2], b1[3]);
        mma16816(acc[1][0], a1, b0[0], b0[1]);
        mma16816(acc[1][1], a1, b0[2], b0[3]);
        mma16816(acc[1][2], a1, b1[0], b1[1]);
        mma16816(acc[1][3], a1, b1[2], b1[3]);
    }
}

/* ---------- K1: 2-term bf16 tensor GEMM + fused top-2/thread argmin ---------- */
__global__ void __launch_bounds__(256, 2) vq_mma_kernel() {
    extern __shared__ __align__(128) unsigned char smem[];
    const unsigned smb = smem_u32(smem);
    const int tid = threadIdx.x;
    const int lane = tid & 31;
    const int w = tid >> 5;
    const int wm = w >> 2, wn = w & 3;
    const int mtile = blockIdx.x;

    { /* resident A (hi|lo, 64KB) */
        const unsigned char* src = g_zt + (size_t)mtile * 65536 + tid * 16;
        unsigned dst = smb + SA_OFF + tid * 16;
#pragma unroll
        for (int i = 0; i < 16; i++) cp_async16(dst + i * 4096, src + (size_t)i * 4096);
        asm volatile("cp.async.commit_group;" ::: "memory");
    }
    issue_chunk(smb, 0, tid);
    issue_chunk(smb, 1, tid);

    float acc[2][4][4];
#pragma unroll
    for (int i = 0; i < 2; i++)
#pragma unroll
        for (int j = 0; j < 4; j++)
#pragma unroll
            for (int r = 0; r < 4; r++) acc[i][j][r] = 0.f;
    float tv1[4], tv2[4];
    int ti1[4], ti2[4];
#pragma unroll
    for (int sl = 0; sl < 4; sl++) { tv1[sl] = CUDART_INF_F; tv2[sl] = CUDART_INF_F; ti1[sl] = 0; ti2[sl] = 0; }

    for (int s = 0; s < NCHUNK; s++) {
        if (s == NCHUNK - 1) asm volatile("cp.async.wait_group 0;" ::: "memory");
        else                 asm volatile("cp.async.wait_group 1;" ::: "memory");
        __syncthreads();
        const int p = s & 3, buf = s & 1;
        mma_pass(acc, smb, p,     buf, wm, wn, lane);   /* A_hi x B_hi */
        mma_pass(acc, smb, 4 + p, buf, wm, wn, lane);   /* A_lo x B_hi */
        if (p == 3) {                                   /* epilogue: dist + top-2 */
            const int nt = s >> 2;
            const float* cnp = (const float*)(smem + SCN_OFF + (nt & 1) * 512);
            const int colb = wn * 32 + 2 * (lane & 3);
#pragma unroll
            for (int ni = 0; ni < 4; ni++) {
                float cn0 = cnp[colb + ni * 8];
                float cn1 = cnp[colb + ni * 8 + 1];
                int c0 = nt * 128 + colb + ni * 8;
#pragma unroll
                for (int mi = 0; mi < 2; mi++) {
#pragma unroll
                    for (int h = 0; h < 2; h++) {
                        int sl = mi * 2 + h;
                        float d0 = fmaf(-2.f, acc[mi][ni][h * 2],     cn0);
                        float d1 = fmaf(-2.f, acc[mi][ni][h * 2 + 1], cn1);
                        top2_update(tv1[sl], ti1[sl], tv2[sl], ti2[sl], d0, c0);
                        top2_update(tv1[sl], ti1[sl], tv2[sl], ti2[sl], d1, c0 + 1);
                        acc[mi][ni][h * 2] = 0.f;
                        acc[mi][ni][h * 2 + 1] = 0.f;
                    }
                }
            }
        }
        __syncthreads();
        if (s + 2 < NCHUNK) issue_chunk(smb, s + 2, tid);
    }

    /* dump all 32 per-row candidates, then per-row top-4 merge */
    __syncthreads();
    float4* red = (float4*)(smem + SB_OFF);    /* 64 rows x 16 entries x 16B */
#pragma unroll
    for (int sl = 0; sl < 4; sl++) {
        int row = wm * 32 + (sl >> 1) * 16 + (sl & 1) * 8 + (lane >> 2);
        red[row * 16 + wn * 4 + (lane & 3)] =
            make_float4(tv1[sl], __int_as_float(ti1[sl]), tv2[sl], __int_as_float(ti2[sl]));
    }
    __syncthreads();
    if (tid < 64) {
        float cv[4] = {CUDART_INF_F, CUDART_INF_F, CUDART_INF_F, CUDART_INF_F};
        int ci[4] = {0x7fffffff, 0x7fffffff, 0x7fffffff, 0x7fffffff};
#pragma unroll
        for (int e = 0; e < 16; e++) {
            float4 f = red[tid * 16 + e];
            ins4(cv, ci, f.x, __float_as_int(f.y));
            ins4(cv, ci, f.z, __float_as_int(f.w));
        }
        *(int4*)(g_cand + (size_t)(mtile * MT + tid) * 4) = make_int4(ci[0], ci[1], ci[2], ci[3]);
    }
}

/* ---------- K2: exact fp32 rescore of top-4 + gather + loss partials ---------- */
__global__ void rescore_gather_kernel(const float* __restrict__ z,
                                      const float* __restrict__ cb,
                                      float* __restrict__ out) {
    const int lane = threadIdx.x & 31, warp = threadIdx.x >> 5;
    const int row = blockIdx.x * 8 + warp;
    __shared__ float wsum[8];

    const int4 cc = *(const int4*)(g_cand + (size_t)row * 4);
    const int cand[4] = {cc.x, cc.y, cc.z, cc.w};
    const float4* z4 = (const float4*)(z + (size_t)row * DIM);
    float4 a[2], b[4][2];
    float d[4] = {0.f, 0.f, 0.f, 0.f};
#pragma unroll
    for (int l = 0; l < 2; l++) {
        int f = lane + 32 * l;
        a[l] = z4[f];
#pragma unroll
        for (int q = 0; q < 4; q++) {
            b[q][l] = ((const float4*)(cb + (size_t)cand[q] * DIM))[f];
            d[q] += a[l].x * b[q][l].x + a[l].y * b[q][l].y
                  + a[l].z * b[q][l].z + a[l].w * b[q][l].w;
        }
    }
#pragma unroll
    for (int o = 16; o > 0; o >>= 1)
#pragma unroll
        for (int q = 0; q < 4; q++) d[q] += __shfl_xor_sync(0xffffffffu, d[q], o);

    float bv = CUDART_INF_F; int bq = 0, bi = 0x7fffffff;
#pragma unroll
    for (int q = 0; q < 4; q++) {
        float dist = fmaf(-2.f, d[q], __ldg(&g_codenorm[cand[q]]));
        if (dist < bv || (dist == bv && cand[q] < bi)) { bv = dist; bi = cand[q]; bq = q; }
    }

    float* out_ze = out + (size_t)row * DIM;
    float* out_zq = out + (size_t)NROWS * DIM + 1 + (size_t)row * DIM;
    float s = 0.f;
#pragma unroll
    for (int l = 0; l < 2; l++) {
        int f = lane + 32 * l;
        float4 ze = a[l];
        float4 zq = b[bq][l];
        *(float4*)(out_ze + f * 4) = ze;
        out_zq[f * 4 + 0] = zq.x; out_zq[f * 4 + 1] = zq.y;
        out_zq[f * 4 + 2] = zq.z; out_zq[f * 4 + 3] = zq.w;
        float dx = zq.x - ze.x, dy = zq.y - ze.y, dz = zq.z - ze.z, dw = zq.w - ze.w;
        s += dx * dx + dy * dy + dz * dz + dw * dw;
    }
#pragma unroll
    for (int o = 16; o > 0; o >>= 1) s += __shfl_down_sync(0xffffffffu, s, o);
    if (lane == 0) wsum[warp] = s;
    __syncthreads();
    if (threadIdx.x == 0) {
        float t = 0.f;
#pragma unroll
        for (int wv = 0; wv < 8; wv++) t += wsum[wv];
        g_losspart[blockIdx.x] = t;
    }
}

/* ---------- K3: deterministic final loss ---------- */
__global__ void loss_kernel(float* __restrict__ out) {
    __shared__ float s[256];
    float t = 0.f;
    for (int i = threadIdx.x; i < NPART; i += 256) t += g_losspart[i];
    s[threadIdx.x] = t;
    __syncthreads();
    for (int o = 128; o > 0; o >>= 1) {
        if (threadIdx.x < o) s[threadIdx.x] += s[threadIdx.x + o];
        __syncthreads();
    }
    if (threadIdx.x == 0)
        out[(size_t)NROWS * DIM] = 2.f * s[0] / (float)((size_t)NROWS * DIM);
}

extern "C" void kernel_launch(void* const* d_in, const int* in_sizes, int n_in,
                              void* d_out, int out_size) {
    const float* z  = (const float*)d_in[0];
    const float* cb = (const float*)d_in[1];
    float* out = (float*)d_out;

    cudaFuncSetAttribute(vq_mma_kernel, cudaFuncAttributeMaxDynamicSharedMemorySize, GEMM_SMEM);

    split_z_kernel<<<NROWS * 32 / 256, 256>>>(z);
    split_cb_kernel<<<NTILES * 4, 256>>>(cb);
    codenorm_kernel<<<KCB / 8, 256>>>(cb);
    vq_mma_kernel<<<MTILES, 256, GEMM_SMEM>>>();
    rescore_gather_kernel<<<NROWS / 8, 256>>>(z, cb, out);
    loss_kernel<<<1, 256>>>(out);
}

// round 5
// speedup vs baseline: 7.0410x; 1.4792x over previous
#include <cuda_runtime.h>
#include <cuda_fp16.h>
#include <math_constants.h>
#include <cstdint>

#define NROWS 16384
#define DIM   256
#define KCB   8192
#define MT    64                 /* rows per CTA          */
#define MTILES (NROWS / MT)      /* 256 CTAs              */
#define NTILES (KCB / 128)       /* 64 code tiles         */
#define NCHUNK (4 * NTILES)      /* 256 B chunks          */
#define NPART (NROWS / 8)

/* GEMM smem layout (dynamic) */
#define SA_OFF  0                /* 4 chunks x 8KB = 32768 (A fp16)       */
#define SB_OFF  32768            /* 3 x 16KB B ring / reduce space        */
#define SCN_OFF 81920            /* 2 x 512B codenorm tiles               */
#define GEMM_SMEM 82944

/* ------------- device globals (no allocs allowed) ------------- */
__device__ unsigned char g_zt[MTILES * 32768];          /* 8MB pre-swizzled A fp16 */
__device__ unsigned char g_cbt[NTILES * 4 * 16384];     /* 4MB pre-swizzled B fp16 */
__device__ float g_codenorm[KCB];
__device__ int   g_cand[NROWS * 4];
__device__ float g_losspart[NPART];

/* ------------- helpers ------------- */
__device__ __forceinline__ unsigned smem_u32(const void* p) {
    unsigned a;
    asm("{ .reg .u64 t; cvta.to.shared.u64 t, %1; cvt.u32.u64 %0, t; }" : "=r"(a) : "l"(p));
    return a;
}
__device__ __forceinline__ void cp_async16(unsigned dst, const void* src) {
    asm volatile("cp.async.cg.shared.global [%0], [%1], 16;" :: "r"(dst), "l"(src) : "memory");
}
__device__ __forceinline__ void ldsm_x4(unsigned* r, unsigned addr) {
    asm volatile("ldmatrix.sync.aligned.m8n8.x4.shared.b16 {%0,%1,%2,%3}, [%4];"
                 : "=r"(r[0]), "=r"(r[1]), "=r"(r[2]), "=r"(r[3]) : "r"(addr));
}
__device__ __forceinline__ void ldsm_x4_t(unsigned* r, unsigned addr) {
    asm volatile("ldmatrix.sync.aligned.m8n8.x4.trans.shared.b16 {%0,%1,%2,%3}, [%4];"
                 : "=r"(r[0]), "=r"(r[1]), "=r"(r[2]), "=r"(r[3]) : "r"(addr));
}
__device__ __forceinline__ void mma16816(float (&c)[4], const unsigned* a, unsigned b0, unsigned b1) {
    asm volatile("mma.sync.aligned.m16n8k16.row.col.f32.f16.f16.f32 "
                 "{%0,%1,%2,%3}, {%4,%5,%6,%7}, {%8,%9}, {%0,%1,%2,%3};"
                 : "+f"(c[0]), "+f"(c[1]), "+f"(c[2]), "+f"(c[3])
                 : "r"(a[0]), "r"(a[1]), "r"(a[2]), "r"(a[3]), "r"(b0), "r"(b1));
}
__device__ __forceinline__ void top2_update(float& v1, int& i1, float& v2, int& i2, float d, int c) {
    if (d < v2) {
        if (d < v1) { v2 = v1; i2 = i1; v1 = d; i1 = c; }
        else        { v2 = d;  i2 = c; }
    }
}
__device__ __forceinline__ void ins4(float (&cv)[4], int (&ci)[4], float v, int i) {
#pragma unroll
    for (int j = 0; j < 4; j++) {
        bool lt = (v < cv[j]) || (v == cv[j] && i < ci[j]);
        float tv = lt ? cv[j] : v; int ti = lt ? ci[j] : i;
        if (lt) { cv[j] = v; ci[j] = i; }
        v = tv; i = ti;
    }
}

/* ---------- preprocess: z -> swizzled fp16 tiles ---------- */
__global__ void split_z_kernel(const float* __restrict__ z) {
    const int id = blockIdx.x * 256 + threadIdx.x;
    const int row = id >> 5;
    const int j = id & 31;
    const float* src = z + (size_t)row * DIM + j * 8;
    float4 f0 = __ldg((const float4*)src);
    float4 f1 = __ldg((const float4*)(src + 4));
    float v[8] = {f0.x, f0.y, f0.z, f0.w, f1.x, f1.y, f1.z, f1.w};
    unsigned short hv[8];
#pragma unroll
    for (int e = 0; e < 8; e++) hv[e] = __half_as_ushort(__float2half_rn(v[e]));
    const int m = row & 63;
    const int kc = j >> 3, c = j & 7;
    size_t base = (size_t)(row >> 6) * 32768 + (size_t)kc * 8192 + m * 128 + ((c ^ (m & 7)) << 4);
    *(uint4*)(g_zt + base) = *(uint4*)hv;
}

/* ---------- preprocess: codebook -> k-major swizzled fp16 chunks ---------- */
__global__ void split_cb_kernel(const float* __restrict__ cb) {
    __shared__ __half sh[64][136];
    const int nt = blockIdx.x >> 2;
    const int kc = blockIdx.x & 3;
    const int tid = threadIdx.x;
    const int n = tid >> 1, half = tid & 1;
    const float* src = cb + (size_t)(nt * 128 + n) * DIM + kc * 64 + half * 32;
#pragma unroll
    for (int j = 0; j < 8; j++) {
        float4 f = __ldg((const float4*)(src + j * 4));
        float vv[4] = {f.x, f.y, f.z, f.w};
#pragma unroll
        for (int e = 0; e < 4; e++) {
            int k = half * 32 + j * 4 + e;
            sh[k][n] = __float2half_rn(vv[e]);
        }
    }
    __syncthreads();
    unsigned char* dhi = g_cbt + ((size_t)nt * 4 + kc) * 16384;
#pragma unroll
    for (int i = 0; i < 4; i++) {
        int u = tid + i * 256;
        int k = u >> 4, c = u & 15;
        unsigned short hv[8];
#pragma unroll
        for (int e = 0; e < 8; e++) hv[e] = __half_as_ushort(sh[k][c * 8 + e]);
        size_t off = (size_t)k * 256 + ((c ^ (k & 7)) * 16);
        *(uint4*)(dhi + off) = *(uint4*)hv;
    }
}

/* ---------- exact fp32 codebook norms ---------- */
__global__ void codenorm_kernel(const float* __restrict__ cb) {
    int warp = threadIdx.x >> 5, lane = threadIdx.x & 31;
    int row = blockIdx.x * 8 + warp;
    const float4* c4 = (const float4*)(cb + (size_t)row * DIM);
    float s = 0.f;
#pragma unroll
    for (int l = 0; l < 2; l++) {
        float4 v = c4[lane + 32 * l];
        s += v.x * v.x + v.y * v.y + v.z * v.z + v.w * v.w;
    }
#pragma unroll
    for (int o = 16; o > 0; o >>= 1) s += __shfl_down_sync(0xffffffffu, s, o);
    if (lane == 0) g_codenorm[row] = s;
}

/* ---------- B-chunk producer (into 3-slot ring buffer wb) ---------- */
__device__ __forceinline__ void issue_chunk(unsigned smb, int s, int wb, int tid) {
    const int nt = s >> 2, p = s & 3;
    const unsigned char* src = g_cbt + ((size_t)nt * 4 + p) * 16384 + tid * 16;
    unsigned dst = smb + SB_OFF + wb * 16384 + tid * 16;
#pragma unroll
    for (int i = 0; i < 4; i++) cp_async16(dst + i * 4096, src + (size_t)i * 4096);
    if (p == 0 && tid < 32)
        cp_async16(smb + SCN_OFF + (nt & 1) * 512 + tid * 16,
                   (const unsigned char*)g_codenorm + (size_t)nt * 512 + tid * 16);
    asm volatile("cp.async.commit_group;" ::: "memory");
}

/* ---------- one k64 x (64m x 128n) mma pass ---------- */
__device__ __forceinline__ void mma_pass(float (&acc)[2][4][4], unsigned smb,
                                         int achunk, int buf, int wm, int wn, int lane) {
    const unsigned abase = smb + SA_OFF + achunk * 8192;
    const unsigned bbase = smb + SB_OFF + buf * 16384;
    const int mlo = wm * 32 + (lane & 15);
    const int mhi = mlo + 16;
    const int klane = lane & 15;
    const int sel = lane >> 4;
#pragma unroll
    for (int ks = 0; ks < 4; ks++) {
        unsigned a0[4], a1[4], b0[4], b1[4];
        {
            int kc16 = ks * 2 + sel;
            ldsm_x4(a0, abase + mlo * 128 + ((kc16 ^ (mlo & 7)) << 4));
            ldsm_x4(a1, abase + mhi * 128 + ((kc16 ^ (mhi & 7)) << 4));
        }
        {
            int k = ks * 16 + klane;
            int cbase = wn * 4 + sel;
            ldsm_x4_t(b0, bbase + k * 256 + ((cbase ^ (k & 7)) << 4));
            ldsm_x4_t(b1, bbase + k * 256 + (((cbase + 2) ^ (k & 7)) << 4));
        }
        mma16816(acc[0][0], a0, b0[0], b0[1]);
        mma16816(acc[0][1], a0, b0[2], b0[3]);
        mma16816(acc[0][2], a0, b1[0], b1[1]);
        mma16816(acc[0][3], a0, b1[2], b1[3]);
        mma16816(acc[1][0], a1, b0[0], b0[1]);
        mma16816(acc[1][1], a1, b0[2], b0[3]);
        mma16816(acc[1][2], a1, b1[0], b1[1]);
        mma16816(acc[1][3], a1, b1[2], b1[3]);
    }
}

/* ---------- K1: fp16 tensor GEMM + fused top-2/thread argmin ---------- */
__global__ void __launch_bounds__(256, 2) vq_mma_kernel() {
    extern __shared__ __align__(128) unsigned char smem[];
    const unsigned smb = smem_u32(smem);
    const int tid = threadIdx.x;
    const int lane = tid & 31;
    const int w = tid >> 5;
    const int wm = w >> 2, wn = w & 3;
    const int mtile = blockIdx.x;

    { /* resident A (fp16, 32KB) */
        const unsigned char* src = g_zt + (size_t)mtile * 32768 + tid * 16;
        unsigned dst = smb + SA_OFF + tid * 16;
#pragma unroll
        for (int i = 0; i < 8; i++) cp_async16(dst + i * 4096, src + (size_t)i * 4096);
        asm volatile("cp.async.commit_group;" ::: "memory");
    }
    issue_chunk(smb, 0, 0, tid);
    issue_chunk(smb, 1, 1, tid);

    float acc[2][4][4];
#pragma unroll
    for (int i = 0; i < 2; i++)
#pragma unroll
        for (int j = 0; j < 4; j++)
#pragma unroll
            for (int r = 0; r < 4; r++) acc[i][j][r] = 0.f;
    float tv1[4], tv2[4];
    int ti1[4], ti2[4];
#pragma unroll
    for (int sl = 0; sl < 4; sl++) { tv1[sl] = CUDART_INF_F; tv2[sl] = CUDART_INF_F; ti1[sl] = 0; ti2[sl] = 0; }

    int rbuf = 0, wbuf = 2;   /* 3-slot ring: read buf of chunk s, write buf of chunk s+2 */
    for (int s = 0; s < NCHUNK; s++) {
        if (s == NCHUNK - 1) asm volatile("cp.async.wait_group 0;" ::: "memory");
        else                 asm volatile("cp.async.wait_group 1;" ::: "memory");
        __syncthreads();
        if (s + 2 < NCHUNK) issue_chunk(smb, s + 2, wbuf, tid);
        const int p = s & 3;
        mma_pass(acc, smb, p, rbuf, wm, wn, lane);
        if (p == 3) {                                   /* epilogue: dist + top-2 */
            const int nt = s >> 2;
            const float* cnp = (const float*)(smem + SCN_OFF + (nt & 1) * 512);
            const int colb = wn * 32 + 2 * (lane & 3);
#pragma unroll
            for (int ni = 0; ni < 4; ni++) {
                float cn0 = cnp[colb + ni * 8];
                float cn1 = cnp[colb + ni * 8 + 1];
                int c0 = nt * 128 + colb + ni * 8;
#pragma unroll
                for (int mi = 0; mi < 2; mi++) {
#pragma unroll
                    for (int h = 0; h < 2; h++) {
                        int sl = mi * 2 + h;
                        float d0 = fmaf(-2.f, acc[mi][ni][h * 2],     cn0);
                        float d1 = fmaf(-2.f, acc[mi][ni][h * 2 + 1], cn1);
                        top2_update(tv1[sl], ti1[sl], tv2[sl], ti2[sl], d0, c0);
                        top2_update(tv1[sl], ti1[sl], tv2[sl], ti2[sl], d1, c0 + 1);
                        acc[mi][ni][h * 2] = 0.f;
                        acc[mi][ni][h * 2 + 1] = 0.f;
                    }
                }
            }
        }
        rbuf = (rbuf == 2) ? 0 : rbuf + 1;
        wbuf = (wbuf == 2) ? 0 : wbuf + 1;
    }

    /* dump all 32 per-row candidates, then per-row top-4 merge */
    __syncthreads();
    float4* red = (float4*)(smem + SB_OFF);    /* 64 rows x 16 entries x 16B */
#pragma unroll
    for (int sl = 0; sl < 4; sl++) {
        int row = wm * 32 + (sl >> 1) * 16 + (sl & 1) * 8 + (lane >> 2);
        red[row * 16 + wn * 4 + (lane & 3)] =
            make_float4(tv1[sl], __int_as_float(ti1[sl]), tv2[sl], __int_as_float(ti2[sl]));
    }
    __syncthreads();
    if (tid < 64) {
        float cv[4] = {CUDART_INF_F, CUDART_INF_F, CUDART_INF_F, CUDART_INF_F};
        int ci[4] = {0x7fffffff, 0x7fffffff, 0x7fffffff, 0x7fffffff};
#pragma unroll
        for (int e = 0; e < 16; e++) {
            float4 f = red[tid * 16 + e];
            ins4(cv, ci, f.x, __float_as_int(f.y));
            ins4(cv, ci, f.z, __float_as_int(f.w));
        }
        *(int4*)(g_cand + (size_t)(mtile * MT + tid) * 4) = make_int4(ci[0], ci[1], ci[2], ci[3]);
    }
}

/* ---------- K2: exact fp32 rescore of top-4 + gather + loss partials ---------- */
__global__ void rescore_gather_kernel(const float* __restrict__ z,
                                      const float* __restrict__ cb,
                                      float* __restrict__ out) {
    const int lane = threadIdx.x & 31, warp = threadIdx.x >> 5;
    const int row = blockIdx.x * 8 + warp;
    __shared__ float wsum[8];

    const int4 cc = *(const int4*)(g_cand + (size_t)row * 4);
    const int cand[4] = {cc.x, cc.y, cc.z, cc.w};
    const float4* z4 = (const float4*)(z + (size_t)row * DIM);
    float4 a[2], b[4][2];
    float d[4] = {0.f, 0.f, 0.f, 0.f};
#pragma unroll
    for (int l = 0; l < 2; l++) {
        int f = lane + 32 * l;
        a[l] = z4[f];
#pragma unroll
        for (int q = 0; q < 4; q++) {
            b[q][l] = ((const float4*)(cb + (size_t)cand[q] * DIM))[f];
            d[q] += a[l].x * b[q][l].x + a[l].y * b[q][l].y
                  + a[l].z * b[q][l].z + a[l].w * b[q][l].w;
        }
    }
#pragma unroll
    for (int o = 16; o > 0; o >>= 1)
#pragma unroll
        for (int q = 0; q < 4; q++) d[q] += __shfl_xor_sync(0xffffffffu, d[q], o);

    float bv = CUDART_INF_F; int bq = 0, bi = 0x7fffffff;
#pragma unroll
    for (int q = 0; q < 4; q++) {
        float dist = fmaf(-2.f, d[q], __ldg(&g_codenorm[cand[q]]));
        if (dist < bv || (dist == bv && cand[q] < bi)) { bv = dist; bi = cand[q]; bq = q; }
    }

    float* out_ze = out + (size_t)row * DIM;
    float* out_zq = out + (size_t)NROWS * DIM + 1 + (size_t)row * DIM;
    float s = 0.f;
#pragma unroll
    for (int l = 0; l < 2; l++) {
        int f = lane + 32 * l;
        float4 ze = a[l];
        float4 zq = b[bq][l];
        *(float4*)(out_ze + f * 4) = ze;
        out_zq[f * 4 + 0] = zq.x; out_zq[f * 4 + 1] = zq.y;
        out_zq[f * 4 + 2] = zq.z; out_zq[f * 4 + 3] = zq.w;
        float dx = zq.x - ze.x, dy = zq.y - ze.y, dz = zq.z - ze.z, dw = zq.w - ze.w;
        s += dx * dx + dy * dy + dz * dz + dw * dw;
    }
#pragma unroll
    for (int o = 16; o > 0; o >>= 1) s += __shfl_down_sync(0xffffffffu, s, o);
    if (lane == 0) wsum[warp] = s;
    __syncthreads();
    if (threadIdx.x == 0) {
        float t = 0.f;
#pragma unroll
        for (int wv = 0; wv < 8; wv++) t += wsum[wv];
        g_losspart[blockIdx.x] = t;
    }
}

/* ---------- K3: deterministic final loss ---------- */
__global__ void loss_kernel(float* __restrict__ out) {
    __shared__ float s[256];
    float t = 0.f;
    for (int i = threadIdx.x; i < NPART; i += 256) t += g_losspart[i];
    s[threadIdx.x] = t;
    __syncthreads();
    for (int o = 128; o > 0; o >>= 1) {
        if (threadIdx.x < o) s[threadIdx.x] += s[threadIdx.x + o];
        __syncthreads();
    }
    if (threadIdx.x == 0)
        out[(size_t)NROWS * DIM] = 2.f * s[0] / (float)((size_t)NROWS * DIM);
}

extern "C" void kernel_launch(void* const* d_in, const int* in_sizes, int n_in,
                              void* d_out, int out_size) {
    const float* z  = (const float*)d_in[0];
    const float* cb = (const float*)d_in[1];
    float* out = (float*)d_out;

    cudaFuncSetAttribute(vq_mma_kernel, cudaFuncAttributeMaxDynamicSharedMemorySize, GEMM_SMEM);

    split_z_kernel<<<NROWS * 32 / 256, 256>>>(z);
    split_cb_kernel<<<NTILES * 4, 256>>>(cb);
    codenorm_kernel<<<KCB / 8, 256>>>(cb);
    vq_mma_kernel<<<MTILES, 256, GEMM_SMEM>>>();
    rescore_gather_kernel<<<NROWS / 8, 256>>>(z, cb, out);
    loss_kernel<<<1, 256>>>(out);
}

// round 6
// speedup vs baseline: 7.7033x; 1.0941x over previous
#include <cuda_runtime.h>
#include <cuda_fp16.h>
#include <math_constants.h>
#include <cstdint>

#define NROWS 16384
#define DIM   256
#define KCB   8192
#define MT    64                 /* rows per CTA           */
#define MTILES (NROWS / MT)      /* 256 CTAs               */
#define NTILES (KCB / 128)       /* 64 code tiles          */
#define NHALF  (2 * NTILES)      /* 128 k128xn128 halves   */
#define NPART (NROWS / 8)

/* GEMM smem layout (dynamic) */
#define SA_OFF  0                /* A fp16: 4 sub-chunks x 8KB = 32768 */
#define SB_OFF  32768            /* 2 x 32KB B half double buffer      */
#define SCN_OFF 98304            /* 2 x 512B codenorm tiles            */
#define GEMM_SMEM 99328

/* ------------- device globals (no allocs allowed) ------------- */
__device__ unsigned char g_zt[MTILES * 32768];       /* 8MB pre-swizzled A fp16       */
__device__ unsigned char g_cbt[NHALF * 32768];       /* 4MB pre-swizzled B fp16 halves*/
__device__ float g_codenorm[KCB];
__device__ int   g_cand[NROWS * 4];
__device__ float g_losspart[NPART];

/* ------------- helpers ------------- */
__device__ __forceinline__ unsigned smem_u32(const void* p) {
    unsigned a;
    asm("{ .reg .u64 t; cvta.to.shared.u64 t, %1; cvt.u32.u64 %0, t; }" : "=r"(a) : "l"(p));
    return a;
}
__device__ __forceinline__ void cp_async16(unsigned dst, const void* src) {
    asm volatile("cp.async.cg.shared.global [%0], [%1], 16;" :: "r"(dst), "l"(src) : "memory");
}
__device__ __forceinline__ void ldsm_x4(unsigned* r, unsigned addr) {
    asm volatile("ldmatrix.sync.aligned.m8n8.x4.shared.b16 {%0,%1,%2,%3}, [%4];"
                 : "=r"(r[0]), "=r"(r[1]), "=r"(r[2]), "=r"(r[3]) : "r"(addr));
}
__device__ __forceinline__ void ldsm_x4_t(unsigned* r, unsigned addr) {
    asm volatile("ldmatrix.sync.aligned.m8n8.x4.trans.shared.b16 {%0,%1,%2,%3}, [%4];"
                 : "=r"(r[0]), "=r"(r[1]), "=r"(r[2]), "=r"(r[3]) : "r"(addr));
}
__device__ __forceinline__ void mma16816(float (&c)[4], const unsigned* a, unsigned b0, unsigned b1) {
    asm volatile("mma.sync.aligned.m16n8k16.row.col.f32.f16.f16.f32 "
                 "{%0,%1,%2,%3}, {%4,%5,%6,%7}, {%8,%9}, {%0,%1,%2,%3};"
                 : "+f"(c[0]), "+f"(c[1]), "+f"(c[2]), "+f"(c[3])
                 : "r"(a[0]), "r"(a[1]), "r"(a[2]), "r"(a[3]), "r"(b0), "r"(b1));
}
__device__ __forceinline__ void top2_update(float& v1, int& i1, float& v2, int& i2, float d, int c) {
    if (d < v2) {
        if (d < v1) { v2 = v1; i2 = i1; v1 = d; i1 = c; }
        else        { v2 = d;  i2 = c; }
    }
}
__device__ __forceinline__ void ins4(float (&cv)[4], int (&ci)[4], float v, int i) {
#pragma unroll
    for (int j = 0; j < 4; j++) {
        bool lt = (v < cv[j]) || (v == cv[j] && i < ci[j]);
        float tv = lt ? cv[j] : v; int ti = lt ? ci[j] : i;
        if (lt) { cv[j] = v; ci[j] = i; }
        v = tv; i = ti;
    }
}

/* ---------- preprocess: z -> swizzled fp16 tiles (64 rows x 4 k64 sub-chunks) ---------- */
__global__ void split_z_kernel(const float* __restrict__ z) {
    const int id = blockIdx.x * 256 + threadIdx.x;
    const int row = id >> 5;
    const int j = id & 31;
    const float* src = z + (size_t)row * DIM + j * 8;
    float4 f0 = __ldg((const float4*)src);
    float4 f1 = __ldg((const float4*)(src + 4));
    float v[8] = {f0.x, f0.y, f0.z, f0.w, f1.x, f1.y, f1.z, f1.w};
    unsigned short hv[8];
#pragma unroll
    for (int e = 0; e < 8; e++) hv[e] = __half_as_ushort(__float2half_rn(v[e]));
    const int m = row & 63;
    const int kc = j >> 3, c = j & 7;
    size_t base = (size_t)(row >> 6) * 32768 + (size_t)kc * 8192 + m * 128 + ((c ^ (m & 7)) << 4);
    *(uint4*)(g_zt + base) = *(uint4*)hv;
}

/* ---------- preprocess: codebook -> k-major swizzled fp16 32KB halves ---------- */
__global__ void split_cb_kernel(const float* __restrict__ cb) {
    __shared__ __half sh[128][136];
    const int hidx = blockIdx.x;           /* 0..127 */
    const int nt = hidx >> 1, h = hidx & 1;
    const int tid = threadIdx.x;
    const int n = tid >> 1, khalf = (tid & 1) * 64;
    const float* src = cb + (size_t)(nt * 128 + n) * DIM + h * 128 + khalf;
#pragma unroll
    for (int j = 0; j < 16; j++) {
        float4 f = __ldg((const float4*)(src + j * 4));
        sh[khalf + j * 4 + 0][n] = __float2half_rn(f.x);
        sh[khalf + j * 4 + 1][n] = __float2half_rn(f.y);
        sh[khalf + j * 4 + 2][n] = __float2half_rn(f.z);
        sh[khalf + j * 4 + 3][n] = __float2half_rn(f.w);
    }
    __syncthreads();
    unsigned char* dst = g_cbt + (size_t)hidx * 32768;
#pragma unroll
    for (int j = 0; j < 8; j++) {
        int u = tid + j * 256;              /* 0..2047 */
        int k = u >> 4, c = u & 15;
        uint4 v = *(const uint4*)(&sh[k][c * 8]);
        *(uint4*)(dst + (size_t)k * 256 + ((c ^ (k & 7)) << 4)) = v;
    }
}

/* ---------- exact fp32 codebook norms ---------- */
__global__ void codenorm_kernel(const float* __restrict__ cb) {
    int warp = threadIdx.x >> 5, lane = threadIdx.x & 31;
    int row = blockIdx.x * 8 + warp;
    const float4* c4 = (const float4*)(cb + (size_t)row * DIM);
    float s = 0.f;
#pragma unroll
    for (int l = 0; l < 2; l++) {
        float4 v = c4[lane + 32 * l];
        s += v.x * v.x + v.y * v.y + v.z * v.z + v.w * v.w;
    }
#pragma unroll
    for (int o = 16; o > 0; o >>= 1) s += __shfl_down_sync(0xffffffffu, s, o);
    if (lane == 0) g_codenorm[row] = s;
}

/* ---------- B-half producer: 32KB into buffer (s&1), one commit group ---------- */
__device__ __forceinline__ void issue_half(unsigned smb, int s, int tid) {
    const unsigned char* src = g_cbt + (size_t)s * 32768 + tid * 16;
    unsigned dst = smb + SB_OFF + (s & 1) * 32768 + tid * 16;
#pragma unroll
    for (int i = 0; i < 8; i++) cp_async16(dst + i * 4096, src + (size_t)i * 4096);
    if ((s & 1) == 0 && tid < 32)
        cp_async16(smb + SCN_OFF + ((s >> 1) & 1) * 512 + tid * 16,
                   (const unsigned char*)g_codenorm + (size_t)(s >> 1) * 512 + tid * 16);
    asm volatile("cp.async.commit_group;" ::: "memory");
}

/* ---------- compute one k128 half: 8 k16-steps, buf = H ---------- */
template<int H>
__device__ __forceinline__ void compute_half(float (&acc)[2][4][4], unsigned smb,
                                             int wm, int wn, int lane) {
    const int mlo = wm * 32 + (lane & 15);
    const int mhi = mlo + 16;
    const int klane = lane & 15;
    const int sel = lane >> 4;
    const unsigned alo_base = smb + SA_OFF + mlo * 128;
    const unsigned ahi_base = smb + SA_OFF + mhi * 128;
    const int xlo = mlo & 7, xhi = mhi & 7;
    /* B: swizzle XOR is per-thread constant (k&7 == klane&7 for all ks) */
    const int cb0 = wn * 4 + sel;
    const unsigned bb = smb + SB_OFF + H * 32768 + klane * 256;
    const unsigned b0base = bb + (((cb0)     ^ (klane & 7)) << 4);
    const unsigned b1base = bb + (((cb0 + 2) ^ (klane & 7)) << 4);
#pragma unroll
    for (int ks = 0; ks < 8; ks++) {
        const int base_g = H * 16 + ks * 2;        /* compile-time, even */
        const int sub = base_g >> 3;               /* compile-time       */
        unsigned a0[4], a1[4], b0[4], b1[4];
        {
            int kc = (base_g & 7) + sel;           /* stays within 0..7  */
            ldsm_x4(a0, alo_base + sub * 8192 + ((kc ^ xlo) << 4));
            ldsm_x4(a1, ahi_base + sub * 8192 + ((kc ^ xhi) << 4));
        }
        ldsm_x4_t(b0, b0base + ks * 4096);
        ldsm_x4_t(b1, b1base + ks * 4096);
        mma16816(acc[0][0], a0, b0[0], b0[1]);
        mma16816(acc[0][1], a0, b0[2], b0[3]);
        mma16816(acc[0][2], a0, b1[0], b1[1]);
        mma16816(acc[0][3], a0, b1[2], b1[3]);
        mma16816(acc[1][0], a1, b0[0], b0[1]);
        mma16816(acc[1][1], a1, b0[2], b0[3]);
        mma16816(acc[1][2], a1, b1[0], b1[1]);
        mma16816(acc[1][3], a1, b1[2], b1[3]);
    }
}

/* ---------- K1: fp16 tensor GEMM + fused top-2/thread argmin ---------- */
__global__ void __launch_bounds__(256, 2) vq_mma_kernel() {
    extern __shared__ __align__(128) unsigned char smem[];
    const unsigned smb = smem_u32(smem);
    const int tid = threadIdx.x;
    const int lane = tid & 31;
    const int w = tid >> 5;
    const int wm = w >> 2, wn = w & 3;
    const int mtile = blockIdx.x;

    { /* prologue group: resident A (32KB) + half 0 + cn tile 0 */
        const unsigned char* src = g_zt + (size_t)mtile * 32768 + tid * 16;
        unsigned dst = smb + SA_OFF + tid * 16;
#pragma unroll
        for (int i = 0; i < 8; i++) cp_async16(dst + i * 4096, src + (size_t)i * 4096);
        issue_half(smb, 0, tid);   /* commits A + half0 + cn0 as one group */
    }

    float acc[2][4][4];
#pragma unroll
    for (int i = 0; i < 2; i++)
#pragma unroll
        for (int j = 0; j < 4; j++)
#pragma unroll
            for (int r = 0; r < 4; r++) acc[i][j][r] = 0.f;
    float tv1[4], tv2[4];
    int ti1[4], ti2[4];
#pragma unroll
    for (int sl = 0; sl < 4; sl++) { tv1[sl] = CUDART_INF_F; tv2[sl] = CUDART_INF_F; ti1[sl] = 0; ti2[sl] = 0; }

    const int colb = wn * 32 + 2 * (lane & 3);
    for (int ii = 0; ii < NTILES; ii++) {
        /* ---- half 0 of tile ii ---- */
        asm volatile("cp.async.wait_group 0;" ::: "memory");
        __syncthreads();
        issue_half(smb, 2 * ii + 1, tid);
        compute_half<0>(acc, smb, wm, wn, lane);
        /* ---- half 1 of tile ii ---- */
        asm volatile("cp.async.wait_group 0;" ::: "memory");
        __syncthreads();
        if (2 * ii + 2 < NHALF) issue_half(smb, 2 * ii + 2, tid);
        compute_half<1>(acc, smb, wm, wn, lane);
        { /* epilogue: dist + top-2, zero acc */
            const float* cnp = (const float*)(smem + SCN_OFF + (ii & 1) * 512);
#pragma unroll
            for (int ni = 0; ni < 4; ni++) {
                float cn0 = cnp[colb + ni * 8];
                float cn1 = cnp[colb + ni * 8 + 1];
                int c0 = ii * 128 + colb + ni * 8;
#pragma unroll
                for (int mi = 0; mi < 2; mi++) {
#pragma unroll
                    for (int h = 0; h < 2; h++) {
                        int sl = mi * 2 + h;
                        float d0 = fmaf(-2.f, acc[mi][ni][h * 2],     cn0);
                        float d1 = fmaf(-2.f, acc[mi][ni][h * 2 + 1], cn1);
                        top2_update(tv1[sl], ti1[sl], tv2[sl], ti2[sl], d0, c0);
                        top2_update(tv1[sl], ti1[sl], tv2[sl], ti2[sl], d1, c0 + 1);
                        acc[mi][ni][h * 2] = 0.f;
                        acc[mi][ni][h * 2 + 1] = 0.f;
                    }
                }
            }
        }
    }

    /* dump all 32 per-row candidates, then per-row top-4 merge */
    __syncthreads();
    float4* red = (float4*)(smem + SB_OFF);    /* 64 rows x 16 entries x 16B */
#pragma unroll
    for (int sl = 0; sl < 4; sl++) {
        int row = wm * 32 + (sl >> 1) * 16 + (sl & 1) * 8 + (lane >> 2);
        red[row * 16 + wn * 4 + (lane & 3)] =
            make_float4(tv1[sl], __int_as_float(ti1[sl]), tv2[sl], __int_as_float(ti2[sl]));
    }
    __syncthreads();
    if (tid < 64) {
        float cv[4] = {CUDART_INF_F, CUDART_INF_F, CUDART_INF_F, CUDART_INF_F};
        int ci[4] = {0x7fffffff, 0x7fffffff, 0x7fffffff, 0x7fffffff};
#pragma unroll
        for (int e = 0; e < 16; e++) {
            float4 f = red[tid * 16 + e];
            ins4(cv, ci, f.x, __float_as_int(f.y));
            ins4(cv, ci, f.z, __float_as_int(f.w));
        }
        *(int4*)(g_cand + (size_t)(mtile * MT + tid) * 4) = make_int4(ci[0], ci[1], ci[2], ci[3]);
    }
}

/* ---------- K2: exact fp32 rescore of top-4 + gather + loss partials ---------- */
__global__ void rescore_gather_kernel(const float* __restrict__ z,
                                      const float* __restrict__ cb,
                                      float* __restrict__ out) {
    const int lane = threadIdx.x & 31, warp = threadIdx.x >> 5;
    const int row = blockIdx.x * 8 + warp;
    __shared__ float wsum[8];

    const int4 cc = *(const int4*)(g_cand + (size_t)row * 4);
    const int cand[4] = {cc.x, cc.y, cc.z, cc.w};
    const float4* z4 = (const float4*)(z + (size_t)row * DIM);
    float4 a[2], b[4][2];
    float d[4] = {0.f, 0.f, 0.f, 0.f};
#pragma unroll
    for (int l = 0; l < 2; l++) {
        int f = lane + 32 * l;
        a[l] = z4[f];
#pragma unroll
        for (int q = 0; q < 4; q++) {
            b[q][l] = ((const float4*)(cb + (size_t)cand[q] * DIM))[f];
            d[q] += a[l].x * b[q][l].x + a[l].y * b[q][l].y
                  + a[l].z * b[q][l].z + a[l].w * b[q][l].w;
        }
    }
#pragma unroll
    for (int o = 16; o > 0; o >>= 1)
#pragma unroll
        for (int q = 0; q < 4; q++) d[q] += __shfl_xor_sync(0xffffffffu, d[q], o);

    float bv = CUDART_INF_F; int bq = 0, bi = 0x7fffffff;
#pragma unroll
    for (int q = 0; q < 4; q++) {
        float dist = fmaf(-2.f, d[q], __ldg(&g_codenorm[cand[q]]));
        if (dist < bv || (dist == bv && cand[q] < bi)) { bv = dist; bi = cand[q]; bq = q; }
    }

    float* out_ze = out + (size_t)row * DIM;
    float* out_zq = out + (size_t)NROWS * DIM + 1 + (size_t)row * DIM;
    float s = 0.f;
#pragma unroll
    for (int l = 0; l < 2; l++) {
        int f = lane + 32 * l;
        float4 ze = a[l];
        float4 zq = b[bq][l];
        *(float4*)(out_ze + f * 4) = ze;
        out_zq[f * 4 + 0] = zq.x; out_zq[f * 4 + 1] = zq.y;
        out_zq[f * 4 + 2] = zq.z; out_zq[f * 4 + 3] = zq.w;
        float dx = zq.x - ze.x, dy = zq.y - ze.y, dz = zq.z - ze.z, dw = zq.w - ze.w;
        s += dx * dx + dy * dy + dz * dz + dw * dw;
    }
#pragma unroll
    for (int o = 16; o > 0; o >>= 1) s += __shfl_down_sync(0xffffffffu, s, o);
    if (lane == 0) wsum[warp] = s;
    __syncthreads();
    if (threadIdx.x == 0) {
        float t = 0.f;
#pragma unroll
        for (int wv = 0; wv < 8; wv++) t += wsum[wv];
        g_losspart[blockIdx.x] = t;
    }
}

/* ---------- K3: deterministic final loss ---------- */
__global__ void loss_kernel(float* __restrict__ out) {
    __shared__ float s[256];
    float t = 0.f;
    for (int i = threadIdx.x; i < NPART; i += 256) t += g_losspart[i];
    s[threadIdx.x] = t;
    __syncthreads();
    for (int o = 128; o > 0; o >>= 1) {
        if (threadIdx.x < o) s[threadIdx.x] += s[threadIdx.x + o];
        __syncthreads();
    }
    if (threadIdx.x == 0)
        out[(size_t)NROWS * DIM] = 2.f * s[0] / (float)((size_t)NROWS * DIM);
}

extern "C" void kernel_launch(void* const* d_in, const int* in_sizes, int n_in,
                              void* d_out, int out_size) {
    const float* z  = (const float*)d_in[0];
    const float* cb = (const float*)d_in[1];
    float* out = (float*)d_out;

    cudaFuncSetAttribute(vq_mma_kernel, cudaFuncAttributeMaxDynamicSharedMemorySize, GEMM_SMEM);

    split_z_kernel<<<NROWS * 32 / 256, 256>>>(z);
    split_cb_kernel<<<NHALF, 256>>>(cb);
    codenorm_kernel<<<KCB / 8, 256>>>(cb);
    vq_mma_kernel<<<MTILES, 256, GEMM_SMEM>>>();
    rescore_gather_kernel<<<NROWS / 8, 256>>>(z, cb, out);
    loss_kernel<<<1, 256>>>(out);
}